// round 7
// baseline (speedup 1.0000x reference)
#include <cuda_runtime.h>
#include <math.h>

// x, x_r: (1, 3, 32, 512, 512) float32
// patch: hc=wc=32 -> 16x16 patches/frame, 32 frames -> 8192 patches of 3*32*32=3072 elems
// P = mean(|x - x_r| * 0.5) per patch ; out = log( mean_t( max(0, max_p P) ) )
//
// One WARP per patch: 768 float4 per tensor = 24 f4/lane, warp-shuffle reduce,
// one atomicMax per warp. No __syncthreads in the hot path.
// Grid: 1184 CTAs x 8 warps = 9472 warp slots >= 8192 patches (single wave, <=1 patch/warp).

#define C_STRIDE4  (32 * 512 * 512 / 4)
#define T_STRIDE4  (512 * 512 / 4)
#define W4         128
#define NPATCH     8192
#define NFRAME     32
#define NCTA       1184
#define NWARPS     (NCTA * 8)

__device__ int          g_M[NFRAME];   // per-frame max (float bits, all >= 0); 0-init = clamp(0)
__device__ unsigned int g_count;       // CTA completion counter

__global__ __launch_bounds__(256, 8) void patch_loss_fused(
    const float4* __restrict__ x, const float4* __restrict__ xr,
    float* __restrict__ out)
{
    const int tid  = threadIdx.x;
    const int lane = tid & 31;
    const int gw   = blockIdx.x * 8 + (tid >> 5);   // global warp id

    for (int p = gw; p < NPATCH; p += NWARPS) {     // executes at most once
        const int t  = p >> 8;
        const int ph = (p >> 4) & 15;
        const int pw = p & 15;
        const int base4 = t * T_STRIDE4 + (ph * 32) * W4 + pw * 8;

        float acc = 0.0f;
        #pragma unroll 3
        for (int k = 0; k < 24; k++) {
            const int f   = lane + (k << 5);   // 0..767 f4 index within patch
            const int c   = f >> 8;            // channel
            const int rem = f & 255;
            const int r   = rem >> 3;          // row in patch
            const int c4  = rem & 7;           // f4 within row
            const int idx = base4 + c * C_STRIDE4 + r * W4 + c4;
            float4 a = x[idx];
            float4 b = xr[idx];
            acc += fabsf(a.x - b.x) + fabsf(a.y - b.y)
                 + fabsf(a.z - b.z) + fabsf(a.w - b.w);
        }

        #pragma unroll
        for (int o = 16; o > 0; o >>= 1)
            acc += __shfl_down_sync(0xFFFFFFFFu, acc, o);

        if (lane == 0) {
            const float P = acc * (0.5f / 3072.0f);
            atomicMax(&g_M[t], __float_as_int(P));   // valid: P >= 0
        }
    }

    // completion handshake (per CTA)
    __shared__ bool last;
    __syncthreads();
    if (tid == 0) {
        __threadfence();
        const unsigned int old = atomicAdd(&g_count, 1u);
        last = (old == NCTA - 1);
    }
    __syncthreads();

    if (last) {
        __threadfence();
        if (tid < 32) {
            float v = __int_as_float(__ldcg(&g_M[tid]));
            #pragma unroll
            for (int o = 16; o > 0; o >>= 1)
                v += __shfl_down_sync(0xFFFFFFFFu, v, o);
            if (tid == 0) {
                out[0] = logf(v * (1.0f / 32.0f));
                g_count = 0;               // reset for next graph replay
            }
            g_M[tid] = 0;
        }
    }
}

extern "C" void kernel_launch(void* const* d_in, const int* in_sizes, int n_in,
                              void* d_out, int out_size)
{
    const float4* x  = (const float4*)d_in[0];
    const float4* xr = (const float4*)d_in[1];
    patch_loss_fused<<<NCTA, 256>>>(x, xr, (float*)d_out);
}

// round 8
// speedup vs baseline: 1.0662x; 1.0662x over previous
#include <cuda_runtime.h>
#include <math.h>

// x, x_r: (1, 3, 32, 512, 512) float32
// patch: hc=wc=32 -> 16x16 patches/frame, 32 frames -> 8192 patches of 3*32*32=3072 elems
// P = mean(|x - x_r| * 0.5) per patch ; out = log( mean_t( max(0, max_p P) ) )
//
// Persistent grid: 1184 CTAs (148 SM x 8 via launch_bounds), 256 threads.
// CTA processes up to 7 patches (p = bid + 1184*i). NO barrier inside the loop:
// warp w writes its partial for iteration i to s_part[i][w] (exclusive slot).
// One __syncthreads at the end, then 7 finalizer threads -> atomicMax per patch.

#define C_STRIDE4  (32 * 512 * 512 / 4)
#define T_STRIDE4  (512 * 512 / 4)
#define W4         128
#define NPATCH     8192
#define NFRAME     32
#define NCTA       1184
#define MAXIT      7                    // ceil(8192 / 1184)

__device__ int          g_M[NFRAME];   // per-frame max (float bits, all >= 0); 0-init = clamp(0)
__device__ unsigned int g_count;       // CTA completion counter

__global__ __launch_bounds__(256, 8) void patch_loss_fused(
    const float4* __restrict__ x, const float4* __restrict__ xr,
    float* __restrict__ out)
{
    const int tid  = threadIdx.x;
    const int lane = tid & 31;
    const int w    = tid >> 5;

    __shared__ float s_part[MAXIT][8];
    __shared__ bool  last;

    int it = 0;
    for (int p = blockIdx.x; p < NPATCH; p += NCTA, it++) {
        const int t  = p >> 8;              // frame
        const int ph = (p >> 4) & 15;       // patch row
        const int pw = p & 15;              // patch col
        const int base4 = t * T_STRIDE4 + (ph * 32) * W4 + pw * 8;

        float acc = 0.0f;
        #pragma unroll
        for (int k = 0; k < 3; k++) {
            const int f   = tid + (k << 8);   // float4-index within patch 0..767
            const int c   = f >> 8;           // channel
            const int rem = f & 255;
            const int r   = rem >> 3;         // row in patch
            const int c4  = rem & 7;          // float4 in row
            const int idx = base4 + c * C_STRIDE4 + r * W4 + c4;
            float4 a = x[idx];
            float4 b = xr[idx];
            acc += fabsf(a.x - b.x) + fabsf(a.y - b.y)
                 + fabsf(a.z - b.z) + fabsf(a.w - b.w);
        }

        #pragma unroll
        for (int o = 16; o > 0; o >>= 1)
            acc += __shfl_down_sync(0xFFFFFFFFu, acc, o);

        if (lane == 0) s_part[it][w] = acc;   // exclusive slot: no barrier needed
    }

    __syncthreads();   // single barrier: all warps' partials visible

    // 7 finalizer threads, one per patch handled by this CTA
    if (tid < MAXIT) {
        const int p = blockIdx.x + tid * NCTA;
        if (p < NPATCH) {
            const float* sp = s_part[tid];
            float v = ((sp[0] + sp[1]) + (sp[2] + sp[3]))
                    + ((sp[4] + sp[5]) + (sp[6] + sp[7]));
            const float P = v * (0.5f / 3072.0f);
            atomicMax(&g_M[p >> 8], __float_as_int(P));   // valid: P >= 0
        }
    }

    // completion handshake
    if (tid == 0) {
        __threadfence();
        const unsigned int old = atomicAdd(&g_count, 1u);
        last = (old == NCTA - 1);
    }
    __syncthreads();

    if (last) {
        __threadfence();
        if (tid < 32) {
            float v = __int_as_float(__ldcg(&g_M[tid]));
            #pragma unroll
            for (int o = 16; o > 0; o >>= 1)
                v += __shfl_down_sync(0xFFFFFFFFu, v, o);
            if (tid == 0) {
                out[0] = logf(v * (1.0f / 32.0f));
                g_count = 0;               // reset for next graph replay
            }
            g_M[tid] = 0;
        }
    }
}

extern "C" void kernel_launch(void* const* d_in, const int* in_sizes, int n_in,
                              void* d_out, int out_size)
{
    const float4* x  = (const float4*)d_in[0];
    const float4* xr = (const float4*)d_in[1];
    patch_loss_fused<<<NCTA, 256>>>(x, xr, (float*)d_out);
}